// round 11
// baseline (speedup 1.0000x reference)
#include <cuda_runtime.h>
#include <cuda_fp16.h>
#include <cstdint>
#include <math.h>

#define NE   8
#define HD   1024
#define FD   4096
#define NT   8192      // B*S tokens
#define CAP  8192      // per-expert worst-case capacity

// ---------------- scratch (device globals; no allocations allowed) ----------
__device__ float g_h[(size_t)NE * CAP * FD];   // 1 GiB  : gelu(x@w1+b1)
__device__ float g_y[(size_t)NE * CAP * HD];   // 256 MiB: h@w2+b2
__device__ int   g_tok[NE * CAP];
__device__ int   g_cnt[NE];
__device__ int   g_slot[NT * 2];
__device__ float g_wt[NT * 2];

// ---------------- helpers ----------------------------------------------------
__device__ __forceinline__ uint32_t packh2(float a, float b) {
    __half2 h = __floats2half2_rn(a, b);
    return *reinterpret_cast<uint32_t*>(&h);
}

__device__ __forceinline__ float gelu_tanh(float v) {
    const float c = 0.7978845608028654f;  // sqrt(2/pi)
    float t = tanhf(c * (v + 0.044715f * v * v * v));
    return 0.5f * v * (1.0f + t);
}

__device__ __forceinline__ void mma_f16(float d[4], const uint32_t a[4], const uint32_t b[2]) {
    asm volatile(
        "mma.sync.aligned.m16n8k16.row.col.f32.f16.f16.f32 "
        "{%0,%1,%2,%3}, {%4,%5,%6,%7}, {%8,%9}, {%0,%1,%2,%3};\n"
        : "+f"(d[0]), "+f"(d[1]), "+f"(d[2]), "+f"(d[3])
        : "r"(a[0]), "r"(a[1]), "r"(a[2]), "r"(a[3]), "r"(b[0]), "r"(b[1]));
}

// ---------------- kernel 0: reset counters -----------------------------------
__global__ void reset_k() {
    if (threadIdx.x < NE) g_cnt[threadIdx.x] = 0;
}

// ---------------- kernel 1: router (one warp per token) -----------------------
__global__ void router_k(const float* __restrict__ x,
                         const float* __restrict__ rw,
                         const float* __restrict__ rb) {
    int gwarp = (blockIdx.x * blockDim.x + threadIdx.x) >> 5;
    int lane  = threadIdx.x & 31;
    if (gwarp >= NT) return;
    const float* xr = x + (size_t)gwarp * HD;

    float acc[NE];
#pragma unroll
    for (int e = 0; e < NE; e++) acc[e] = 0.f;

    for (int h = lane; h < HD; h += 32) {
        float xv = xr[h];
        const float4* w4 = reinterpret_cast<const float4*>(rw + (size_t)h * NE);
        float4 w0 = w4[0], w1 = w4[1];
        acc[0] += xv * w0.x; acc[1] += xv * w0.y;
        acc[2] += xv * w0.z; acc[3] += xv * w0.w;
        acc[4] += xv * w1.x; acc[5] += xv * w1.y;
        acc[6] += xv * w1.z; acc[7] += xv * w1.w;
    }
#pragma unroll
    for (int e = 0; e < NE; e++) {
#pragma unroll
        for (int off = 16; off > 0; off >>= 1)
            acc[e] += __shfl_xor_sync(0xffffffffu, acc[e], off);
    }

    if (lane == 0) {
#pragma unroll
        for (int e = 0; e < NE; e++) acc[e] += rb[e];
        int i0 = 0;
#pragma unroll
        for (int e = 1; e < NE; e++) if (acc[e] > acc[i0]) i0 = e;
        int i1 = (i0 == 0) ? 1 : 0;
#pragma unroll
        for (int e = 0; e < NE; e++)
            if (e != i0 && acc[e] > acc[i1]) i1 = e;

        float w0 = 1.0f / (1.0f + expf(acc[i1] - acc[i0]));

        int s0 = atomicAdd(&g_cnt[i0], 1);
        int s1 = atomicAdd(&g_cnt[i1], 1);
        g_tok[i0 * CAP + s0] = gwarp;
        g_tok[i1 * CAP + s1] = gwarp;
        g_slot[gwarp * 2 + 0] = i0 * CAP + s0;
        g_slot[gwarp * 2 + 1] = i1 * CAP + s1;
        g_wt[gwarp * 2 + 0] = w0;
        g_wt[gwarp * 2 + 1] = 1.0f - w0;
    }
}

// ---------------- kernel 2/3: gathered per-expert GEMM (fp16 mma.sync) --------
// BM=128, BN=256, BK=16. 8 warps in 2x4 grid; 64x64 warp tile (fragment reuse).
// FIRST=true : g_h = gelu(gather(x) @ w1[e] + b1[e]),  K=HD, N=FD
// FIRST=false: g_y = g_h @ w2[e] + b2[e],              K=FD, N=HD
template <int K, int N, bool FIRST>
__global__ __launch_bounds__(256, 1) void ffn_gemm(const float* __restrict__ X,
                                                   const float* __restrict__ W,
                                                   const float* __restrict__ bias) {
    constexpr int BM = 128, BN = 256, BK = 16;   // BK in fp32 elements (one k16 step)
    constexpr int LDA = 136, LDB = 264;          // padded rows (uint32 units)
    __shared__ uint32_t As[2][BK / 2][LDA];
    __shared__ uint32_t Bs[2][BK / 2][LDB];

    const int e = blockIdx.z;
    const int Me = g_cnt[e];
    const int row0 = blockIdx.y * BM;
    if (row0 >= Me) return;
    const int col0 = blockIdx.x * BN;

    const int tid = threadIdx.x;
    const float* We = W + (size_t)e * K * N;

    // A loader: thread owns 1 row, 2 float4 chunks (8 consecutive k floats)
    const int arow = tid >> 1;
    const int af4  = (tid & 1) * 2;
    const bool avalid = (row0 + arow) < Me;
    const float* aptr;
    if (FIRST) {
        int tok = avalid ? g_tok[e * CAP + row0 + arow] : 0;
        aptr = X + (size_t)tok * K;
    } else {
        aptr = g_h + (size_t)(e * CAP + row0 + arow) * K;
    }
    // B loader: thread owns k-pair row kp, 4 n cols at nq and nq+128
    const int kp = tid >> 5;            // 0..7
    const int nq = (tid & 31) * 4;      // 0..124

    float4 aReg[2], bReg[4];

    auto ldAB = [&](int kb) {
        const int kk = kb * BK;
#pragma unroll
        for (int i = 0; i < 2; i++)
            aReg[i] = avalid
                ? *reinterpret_cast<const float4*>(aptr + kk + (af4 + i) * 4)
                : make_float4(0.f, 0.f, 0.f, 0.f);
        const float* b0 = We + (size_t)(kk + 2 * kp) * N + col0;
        const float* b1 = We + (size_t)(kk + 2 * kp + 1) * N + col0;
        bReg[0] = *reinterpret_cast<const float4*>(b0 + nq);
        bReg[1] = *reinterpret_cast<const float4*>(b1 + nq);
        bReg[2] = *reinterpret_cast<const float4*>(b0 + nq + 128);
        bReg[3] = *reinterpret_cast<const float4*>(b1 + nq + 128);
    };
    auto stAB = [&](int s) {
#pragma unroll
        for (int i = 0; i < 2; i++) {
            int k2 = (af4 + i) * 2;     // float k = (af4+i)*4 .. +3 -> k2, k2+1
            As[s][k2 + 0][arow] = packh2(aReg[i].x, aReg[i].y);
            As[s][k2 + 1][arow] = packh2(aReg[i].z, aReg[i].w);
        }
        uint4 bv;
        bv.x = packh2(bReg[0].x, bReg[1].x);
        bv.y = packh2(bReg[0].y, bReg[1].y);
        bv.z = packh2(bReg[0].z, bReg[1].z);
        bv.w = packh2(bReg[0].w, bReg[1].w);
        *reinterpret_cast<uint4*>(&Bs[s][kp][nq]) = bv;
        bv.x = packh2(bReg[2].x, bReg[3].x);
        bv.y = packh2(bReg[2].y, bReg[3].y);
        bv.z = packh2(bReg[2].z, bReg[3].z);
        bv.w = packh2(bReg[2].w, bReg[3].w);
        *reinterpret_cast<uint4*>(&Bs[s][kp][nq + 128]) = bv;
    };

    const int wid = tid >> 5, lane = tid & 31;
    const int wm = wid >> 2, wn = wid & 3;      // 2 x 4 warp grid, 64x64 per warp
    const int r  = lane >> 2, cq = lane & 3;

    float acc[4][8][4];
#pragma unroll
    for (int mt = 0; mt < 4; mt++)
#pragma unroll
        for (int nt = 0; nt < 8; nt++)
#pragma unroll
            for (int i = 0; i < 4; i++) acc[mt][nt][i] = 0.f;

    constexpr int NK = K / BK;
    ldAB(0);
    stAB(0);
    __syncthreads();

    for (int kb = 0; kb < NK; kb++) {
        const int cur = kb & 1;
        if (kb + 1 < NK) ldAB(kb + 1);

        uint32_t a[4][4], b[8][2];
#pragma unroll
        for (int mt = 0; mt < 4; mt++) {
            int m = wm * 64 + mt * 16 + r;
            a[mt][0] = As[cur][cq][m];          // k = 2cq, 2cq+1
            a[mt][1] = As[cur][cq][m + 8];      // row +8
            a[mt][2] = As[cur][cq + 4][m];      // k + 8
            a[mt][3] = As[cur][cq + 4][m + 8];
        }
#pragma unroll
        for (int nt = 0; nt < 8; nt++) {
            int n = wn * 64 + nt * 8 + r;
            b[nt][0] = Bs[cur][cq][n];
            b[nt][1] = Bs[cur][cq + 4][n];
        }
#pragma unroll
        for (int mt = 0; mt < 4; mt++)
#pragma unroll
            for (int nt = 0; nt < 8; nt++)
                mma_f16(acc[mt][nt], a[mt], b[nt]);

        if (kb + 1 < NK) {
            stAB(cur ^ 1);
            __syncthreads();
        }
    }

    // epilogue
    float* Cp = FIRST ? g_h : g_y;
#pragma unroll
    for (int mt = 0; mt < 4; mt++) {
#pragma unroll
        for (int half = 0; half < 2; half++) {
            int grow = row0 + wm * 64 + mt * 16 + r + half * 8;
            if (grow >= Me) continue;
            size_t cbase = ((size_t)(e * CAP) + grow) * N;
#pragma unroll
            for (int nt = 0; nt < 8; nt++) {
                int col = col0 + wn * 64 + nt * 8 + cq * 2;
                float v0 = acc[mt][nt][half * 2 + 0] + bias[e * N + col];
                float v1 = acc[mt][nt][half * 2 + 1] + bias[e * N + col + 1];
                if (FIRST) { v0 = gelu_tanh(v0); v1 = gelu_tanh(v1); }
                *reinterpret_cast<float2*>(Cp + cbase + col) = make_float2(v0, v1);
            }
        }
    }
}

// ---------------- kernel 4: weighted gather-combine ---------------------------
__global__ void combine_k(float* __restrict__ out) {
    int t = blockIdx.x;
    int s0 = g_slot[2 * t], s1 = g_slot[2 * t + 1];
    float w0 = g_wt[2 * t], w1 = g_wt[2 * t + 1];
    const float4* y0 = reinterpret_cast<const float4*>(g_y + (size_t)s0 * HD);
    const float4* y1 = reinterpret_cast<const float4*>(g_y + (size_t)s1 * HD);
    float4* o = reinterpret_cast<float4*>(out + (size_t)t * HD);
    int i = threadIdx.x;  // 256 threads * float4 = 1024 floats
    float4 a = y0[i], b = y1[i];
    o[i] = make_float4(w0 * a.x + w1 * b.x, w0 * a.y + w1 * b.y,
                       w0 * a.z + w1 * b.z, w0 * a.w + w1 * b.w);
}

// ---------------- launch -------------------------------------------------------
extern "C" void kernel_launch(void* const* d_in, const int* in_sizes, int n_in,
                              void* d_out, int out_size) {
    const float* x  = (const float*)d_in[0];
    const float* rw = (const float*)d_in[1];
    const float* rb = (const float*)d_in[2];
    const float* w1 = (const float*)d_in[3];
    const float* b1 = (const float*)d_in[4];
    const float* w2 = (const float*)d_in[5];
    const float* b2 = (const float*)d_in[6];
    float* out = (float*)d_out;
    (void)in_sizes; (void)n_in; (void)out_size;  // top_k fixed at 2

    reset_k<<<1, 32>>>();
    router_k<<<NT / 8, 256>>>(x, rw, rb);

    dim3 g1(FD / 256, NT / 128, NE);
    ffn_gemm<HD, FD, true><<<g1, 256>>>(x, w1, b1);

    dim3 g2(HD / 256, NT / 128, NE);
    ffn_gemm<FD, HD, false><<<g2, 256>>>(x, w2, b2);

    combine_k<<<NT, 256>>>(out);
}

// round 14
// speedup vs baseline: 1.5674x; 1.5674x over previous
#include <cuda_runtime.h>
#include <cuda_fp16.h>
#include <cstdint>
#include <math.h>

#define NE   8
#define HD   1024
#define FD   4096
#define NT   8192      // B*S tokens
#define CAP  8192      // per-expert worst-case capacity

// ---------------- scratch (device globals; no allocations allowed) ----------
__device__ __half   g_xa [(size_t)NE * CAP * HD];        // gathered x, fp16
__device__ uint32_t g_w1p[(size_t)NE * (HD / 2) * FD];   // w1 k-pair packed half2
__device__ uint32_t g_w2p[(size_t)NE * (FD / 2) * HD];   // w2 k-pair packed half2
__device__ __half   g_h  [(size_t)NE * CAP * FD];        // gelu(x@w1+b1), fp16
__device__ float    g_y  [(size_t)NE * CAP * HD];        // h@w2+b2, fp32
__device__ int      g_tok [NE * CAP];
__device__ int      g_cnt [NE];
__device__ int      g_slot[NT * 2];
__device__ float    g_wt  [NT * 2];

// ---------------- helpers ----------------------------------------------------
__device__ __forceinline__ uint32_t packh2(float a, float b) {
    __half2 h = __floats2half2_rn(a, b);
    return *reinterpret_cast<uint32_t*>(&h);
}
__device__ __forceinline__ uint32_t smem_u32(const void* p) {
    uint32_t a;
    asm("{ .reg .u64 t; cvta.to.shared.u64 t, %1; cvt.u32.u64 %0, t; }" : "=r"(a) : "l"(p));
    return a;
}
__device__ __forceinline__ uint32_t lds32(uint32_t a) {
    uint32_t v;
    asm volatile("ld.shared.b32 %0, [%1];" : "=r"(v) : "r"(a));
    return v;
}
#define CP16Z(dst, src, vb) \
    asm volatile("cp.async.cg.shared.global [%0], [%1], 16, %2;" :: "r"(dst), "l"(src), "r"(vb) : "memory")
#define CP16(dst, src) \
    asm volatile("cp.async.cg.shared.global [%0], [%1], 16;" :: "r"(dst), "l"(src) : "memory")
#define CP_COMMIT() asm volatile("cp.async.commit_group;" ::: "memory")
#define CP_WAIT(n)  asm volatile("cp.async.wait_group %0;" :: "n"(n) : "memory")

__device__ __forceinline__ void ldmx4(uint32_t r[4], uint32_t addr) {
    asm volatile("ldmatrix.sync.aligned.m8n8.x4.shared.b16 {%0,%1,%2,%3}, [%4];"
                 : "=r"(r[0]), "=r"(r[1]), "=r"(r[2]), "=r"(r[3]) : "r"(addr));
}
__device__ __forceinline__ float gelu_tanh(float v) {
    const float c = 0.7978845608028654f;  // sqrt(2/pi)
    float t = tanhf(c * (v + 0.044715f * v * v * v));
    return 0.5f * v * (1.0f + t);
}
__device__ __forceinline__ void mma_f16(float d[4], const uint32_t a[4], const uint32_t b[2]) {
    asm volatile(
        "mma.sync.aligned.m16n8k16.row.col.f32.f16.f16.f32 "
        "{%0,%1,%2,%3}, {%4,%5,%6,%7}, {%8,%9}, {%0,%1,%2,%3};\n"
        : "+f"(d[0]), "+f"(d[1]), "+f"(d[2]), "+f"(d[3])
        : "r"(a[0]), "r"(a[1]), "r"(a[2]), "r"(a[3]), "r"(b[0]), "r"(b[1]));
}

// ---------------- kernel 0: reset counters -----------------------------------
__global__ void reset_k() {
    if (threadIdx.x < NE) g_cnt[threadIdx.x] = 0;
}

// ---------------- kernel 1: router (one warp per token) -----------------------
__global__ void router_k(const float* __restrict__ x,
                         const float* __restrict__ rw,
                         const float* __restrict__ rb) {
    int gwarp = (blockIdx.x * blockDim.x + threadIdx.x) >> 5;
    int lane  = threadIdx.x & 31;
    if (gwarp >= NT) return;
    const float* xr = x + (size_t)gwarp * HD;

    float acc[NE];
#pragma unroll
    for (int e = 0; e < NE; e++) acc[e] = 0.f;

    for (int h = lane; h < HD; h += 32) {
        float xv = xr[h];
        const float4* w4 = reinterpret_cast<const float4*>(rw + (size_t)h * NE);
        float4 w0 = w4[0], w1 = w4[1];
        acc[0] += xv * w0.x; acc[1] += xv * w0.y;
        acc[2] += xv * w0.z; acc[3] += xv * w0.w;
        acc[4] += xv * w1.x; acc[5] += xv * w1.y;
        acc[6] += xv * w1.z; acc[7] += xv * w1.w;
    }
#pragma unroll
    for (int e = 0; e < NE; e++) {
#pragma unroll
        for (int off = 16; off > 0; off >>= 1)
            acc[e] += __shfl_xor_sync(0xffffffffu, acc[e], off);
    }

    if (lane == 0) {
#pragma unroll
        for (int e = 0; e < NE; e++) acc[e] += rb[e];
        int i0 = 0;
#pragma unroll
        for (int e = 1; e < NE; e++) if (acc[e] > acc[i0]) i0 = e;
        int i1 = (i0 == 0) ? 1 : 0;
#pragma unroll
        for (int e = 0; e < NE; e++)
            if (e != i0 && acc[e] > acc[i1]) i1 = e;

        float w0 = 1.0f / (1.0f + expf(acc[i1] - acc[i0]));

        int s0 = atomicAdd(&g_cnt[i0], 1);
        int s1 = atomicAdd(&g_cnt[i1], 1);
        g_tok[i0 * CAP + s0] = gwarp;
        g_tok[i1 * CAP + s1] = gwarp;
        g_slot[gwarp * 2 + 0] = i0 * CAP + s0;
        g_slot[gwarp * 2 + 1] = i1 * CAP + s1;
        g_wt[gwarp * 2 + 0] = w0;
        g_wt[gwarp * 2 + 1] = 1.0f - w0;
    }
}

// ---------------- kernel 2: gather x -> fp16 per-expert rows ------------------
__global__ void gather_k(const float* __restrict__ x) {
    int p = blockIdx.x;                 // pair index
    int slot = g_slot[p];
    int tok = p >> 1;
    const float4* src = reinterpret_cast<const float4*>(x + (size_t)tok * HD);
    uint2* dst = reinterpret_cast<uint2*>(g_xa + (size_t)slot * HD);
    float4 v = src[threadIdx.x];
    uint2 o;
    o.x = packh2(v.x, v.y);
    o.y = packh2(v.z, v.w);
    dst[threadIdx.x] = o;
}

// ---------------- kernel 3: pack weights -> k-pair half2 words ----------------
// wp[e][k2][n] = half2(w[e][2k2][n], w[e][2k2+1][n])  (matches GEMM smem image)
template <int Kd, int Nd, bool FIRST>
__global__ void pack_w(const float* __restrict__ w) {
    uint32_t* wp = FIRST ? g_w1p : g_w2p;
    int e = blockIdx.z, k2 = blockIdx.y;
    int n = blockIdx.x * 256 + threadIdx.x;
    const float* s = w + (size_t)e * Kd * Nd + (size_t)(2 * k2) * Nd + n;
    wp[(size_t)e * (Kd / 2) * Nd + (size_t)k2 * Nd + n] = packh2(s[0], s[Nd]);
}

// ---------------- kernel 4/5: fp16 HMMA GEMM, cp.async 3-stage ----------------
// BM=128, BN=128, BK=16 halfs. 8 warps 4x2; 32x64 warp tile (R8-verified mapping).
// FIRST=true : g_h = gelu(g_xa @ w1 + b1),  K=HD, N=FD
// FIRST=false: g_y = g_h @ w2 + b2,         K=FD, N=HD
template <int K, int N, bool FIRST>
__global__ __launch_bounds__(256, 2) void ffn_gemm(const float* __restrict__ bias) {
    constexpr int BM = 128, BN = 128, BK = 16;
    constexpr int AROW = 48;                  // 32B data + 16B pad (conflict-free ldmatrix)
    constexpr int ASZ = BM * AROW;            // 6144
    constexpr int BROW = 544;                 // 128 words + 8 pad
    constexpr int STG = ASZ + (BK / 2) * BROW;  // 10496 per stage
    constexpr int NK = K / BK;
    __shared__ __align__(16) char sm[3][STG];

    // device-side pointer selection (host cannot pass __device__ symbols!)
    const __half*   Asrc = FIRST ? g_xa : g_h;
    const uint32_t* Bp   = FIRST ? g_w1p : g_w2p;

    const int e = blockIdx.z;
    const int Me = g_cnt[e];
    const int row0 = blockIdx.y * BM;
    if (row0 >= Me) return;
    const int col0 = blockIdx.x * BN;

    const int tid = threadIdx.x;
    const uint32_t sb = smem_u32(sm);

    // ---- loaders (cp.async, 16B chunks) ----
    const int arow = tid >> 1, ach = tid & 1;          // A: 128 rows x 2 chunks
    const uint32_t avb = (row0 + arow < Me) ? 16u : 0u;
    const __half* aS = Asrc + ((size_t)e * CAP + row0 + arow) * K + ach * 8;
    const uint32_t adst = sb + arow * AROW + ach * 16;

    const int bk2 = tid >> 5, bch = tid & 31;          // B: 8 k2-rows x 32 chunks
    const uint32_t* bS = Bp + (size_t)e * (K / 2) * N + (size_t)bk2 * N + col0 + bch * 4;
    const uint32_t bdst = sb + ASZ + bk2 * BROW + bch * 16;

    auto issue = [&](int kb, int s) {
        CP16Z(adst + s * STG, aS + kb * BK, avb);
        CP16(bdst + s * STG, bS + (size_t)kb * (BK / 2) * N);
        CP_COMMIT();
    };

    // ---- fragment addressing (R8-verified mapping) ----
    const int wid = tid >> 5, lane = tid & 31;
    const int wm = wid >> 1, wn = wid & 1;      // 4x2 warps, 32x64 per warp
    const int r = lane >> 2, cq = lane & 3;
    const int aRowL = ((lane >> 3) & 1) * 8 + (lane & 7);   // ldmatrix row-in-tile
    const int aKb   = (lane >> 4) * 16;                     // ldmatrix k byte offset

    float acc[2][8][4];
#pragma unroll
    for (int mt = 0; mt < 2; mt++)
#pragma unroll
        for (int nt = 0; nt < 8; nt++)
#pragma unroll
            for (int i = 0; i < 4; i++) acc[mt][nt][i] = 0.f;

    issue(0, 0);
    issue(1, 1);

    for (int kb = 0; kb < NK; kb++) {
        const int s = kb % 3;
        if (kb == NK - 1) { CP_WAIT(0); } else { CP_WAIT(1); }
        __syncthreads();
        if (kb + 2 < NK) issue(kb + 2, (kb + 2) % 3);

        const uint32_t aB = sb + s * STG;
        const uint32_t bB = aB + ASZ;

        uint32_t a[2][4], b[8][2];
#pragma unroll
        for (int mt = 0; mt < 2; mt++)
            ldmx4(a[mt], aB + (wm * 32 + mt * 16 + aRowL) * AROW + aKb);
#pragma unroll
        for (int nt = 0; nt < 8; nt++) {
            int n = wn * 64 + nt * 8 + r;
            b[nt][0] = lds32(bB + cq * BROW + n * 4);
            b[nt][1] = lds32(bB + (cq + 4) * BROW + n * 4);
        }
#pragma unroll
        for (int mt = 0; mt < 2; mt++)
#pragma unroll
            for (int nt = 0; nt < 8; nt++)
                mma_f16(acc[mt][nt], a[mt], b[nt]);
    }

    // ---- epilogue (same mapping as R8) ----
#pragma unroll
    for (int mt = 0; mt < 2; mt++) {
#pragma unroll
        for (int half = 0; half < 2; half++) {
            int grow = row0 + wm * 32 + mt * 16 + r + half * 8;
            if (grow >= Me) continue;
            size_t cbase = ((size_t)(e * CAP) + grow) * N;
#pragma unroll
            for (int nt = 0; nt < 8; nt++) {
                int col = col0 + wn * 64 + nt * 8 + cq * 2;
                float v0 = acc[mt][nt][half * 2 + 0] + bias[e * N + col];
                float v1 = acc[mt][nt][half * 2 + 1] + bias[e * N + col + 1];
                if (FIRST) {
                    v0 = gelu_tanh(v0); v1 = gelu_tanh(v1);
                    __half2 hv = __floats2half2_rn(v0, v1);
                    *reinterpret_cast<__half2*>(&g_h[cbase + col]) = hv;
                } else {
                    *reinterpret_cast<float2*>(&g_y[cbase + col]) = make_float2(v0, v1);
                }
            }
        }
    }
}

// ---------------- kernel 6: weighted gather-combine ---------------------------
__global__ void combine_k(float* __restrict__ out) {
    int t = blockIdx.x;
    int s0 = g_slot[2 * t], s1 = g_slot[2 * t + 1];
    float w0 = g_wt[2 * t], w1 = g_wt[2 * t + 1];
    const float4* y0 = reinterpret_cast<const float4*>(g_y + (size_t)s0 * HD);
    const float4* y1 = reinterpret_cast<const float4*>(g_y + (size_t)s1 * HD);
    float4* o = reinterpret_cast<float4*>(out + (size_t)t * HD);
    int i = threadIdx.x;  // 256 threads * float4 = 1024 floats
    float4 a = y0[i], b = y1[i];
    o[i] = make_float4(w0 * a.x + w1 * b.x, w0 * a.y + w1 * b.y,
                       w0 * a.z + w1 * b.z, w0 * a.w + w1 * b.w);
}

// ---------------- launch -------------------------------------------------------
extern "C" void kernel_launch(void* const* d_in, const int* in_sizes, int n_in,
                              void* d_out, int out_size) {
    const float* x  = (const float*)d_in[0];
    const float* rw = (const float*)d_in[1];
    const float* rb = (const float*)d_in[2];
    const float* w1 = (const float*)d_in[3];
    const float* b1 = (const float*)d_in[4];
    const float* w2 = (const float*)d_in[5];
    const float* b2 = (const float*)d_in[6];
    float* out = (float*)d_out;
    (void)in_sizes; (void)n_in; (void)out_size;  // top_k fixed at 2

    reset_k<<<1, 32>>>();
    router_k<<<NT / 8, 256>>>(x, rw, rb);
    gather_k<<<NT * 2, 256>>>(x);
    pack_w<HD, FD, true><<<dim3(FD / 256, HD / 2, NE), 256>>>(w1);
    pack_w<FD, HD, false><<<dim3(HD / 256, FD / 2, NE), 256>>>(w2);

    dim3 g1(FD / 128, NT / 128, NE);
    ffn_gemm<HD, FD, true><<<g1, 256>>>(b1);

    dim3 g2(HD / 128, NT / 128, NE);
    ffn_gemm<FD, HD, false><<<g2, 256>>>(b2);

    combine_k<<<NT, 256>>>(out);
}